// round 7
// baseline (speedup 1.0000x reference)
#include <cuda_runtime.h>
#include <string.h>

#define NN 512
#define H  64
#define ED 6
#define NL 4
#define EE (NN*NN)
#define LN_EPS 1e-5f

// Scratch (device globals: no allocations allowed)
__device__ float g_h  [NN*H];
__device__ float g_Hd [NN*H];         // dst-side attention proj (+att_b1), row-major
__device__ float g_HsT[2][H*NN];      // src-side attention proj, DIM-MAJOR [j][s], double buffered
__device__ float g_Av [2][NN*H];      // src-side value proj (+val_b1), row-major, double buffered
__device__ float g_eaT[ED*EE];        // edge_attr transposed: eaT[k][d][s]

__device__ __forceinline__ float warp_sum(float v) {
#pragma unroll
    for (int o = 16; o; o >>= 1) v += __shfl_xor_sync(0xffffffffu, v, o);
    return v;
}
__device__ __forceinline__ float warp_max(float v) {
#pragma unroll
    for (int o = 16; o; o >>= 1) v = fmaxf(v, __shfl_xor_sync(0xffffffffu, v, o));
    return v;
}

// Packed fp32x2 ops (sm_103a): 2 fp32 FMAs per instruction
__device__ __forceinline__ float2 ffma2(float2 a, float2 b, float2 c) {
    unsigned long long ua, ub, uc, ur;
    memcpy(&ua, &a, 8); memcpy(&ub, &b, 8); memcpy(&uc, &c, 8);
    asm("fma.rn.f32x2 %0, %1, %2, %3;" : "=l"(ur) : "l"(ua), "l"(ub), "l"(uc));
    float2 r; memcpy(&r, &ur, 8); return r;
}
__device__ __forceinline__ float2 fadd2(float2 a, float2 b) {
    unsigned long long ua, ub, ur;
    memcpy(&ua, &a, 8); memcpy(&ub, &b, 8);
    asm("add.rn.f32x2 %0, %1, %2;" : "=l"(ur) : "l"(ua), "l"(ub));
    float2 r; memcpy(&r, &ur, 8); return r;
}
__device__ __forceinline__ float2 fmul2(float2 a, float2 b) {
    unsigned long long ua, ub, ur;
    memcpy(&ua, &a, 8); memcpy(&ub, &b, 8);
    asm("mul.rn.f32x2 %0, %1, %2;" : "=l"(ur) : "l"(ua), "l"(ub));
    float2 r; memcpy(&r, &ur, 8); return r;
}

// Per-node tables: Hd = h@Wa[0:64]+b1a (row), HsT = h@Wa[64:128] (dim-major), Av = h@Wv[0:64]+b1v (row)
__device__ __forceinline__ void compute_tables(
    int d, int t, int wb, const float* h_sh,
    const float* __restrict__ attW1, const float* __restrict__ attB1,
    const float* __restrict__ valW1, const float* __restrict__ valB1)
{
    float ad = attB1[t], as = 0.f, av = valB1[t];
#pragma unroll 8
    for (int k = 0; k < H; k++) {
        float hk = h_sh[k];
        ad += hk * attW1[k * H + t];
        as += hk * attW1[(H + k) * H + t];
        av += hk * valW1[k * H + t];
    }
    g_Hd[d * H + t]       = ad;
    g_HsT[wb][t * NN + d] = as;
    g_Av[wb][d * H + t]   = av;
}

// Transpose edge_attr: ea[s][d][k] -> eaT[k][d][s]. grid (16,16), block 256.
__global__ void __launch_bounds__(256) ea_transpose_kernel(const float* __restrict__ ea)
{
    __shared__ float t_sh[ED][32][33];
    const int t = threadIdx.x, w = t >> 5, lane = t & 31;
    const int bs = blockIdx.x * 32, bd = blockIdx.y * 32;

#pragma unroll
    for (int rr = 0; rr < 4; rr++) {
        int s_loc = w + rr * 8;
        const float* base = ea + ((size_t)(bs + s_loc) * NN + bd) * ED + lane * ED;
        float2 v0 = *(const float2*)(base);
        float2 v1 = *(const float2*)(base + 2);
        float2 v2 = *(const float2*)(base + 4);
        t_sh[0][lane][s_loc] = v0.x; t_sh[1][lane][s_loc] = v0.y;
        t_sh[2][lane][s_loc] = v1.x; t_sh[3][lane][s_loc] = v1.y;
        t_sh[4][lane][s_loc] = v2.x; t_sh[5][lane][s_loc] = v2.y;
    }
    __syncthreads();
#pragma unroll
    for (int idx = t; idx < ED * 32 * 32; idx += 256) {
        int k = idx >> 10, r = idx & 1023, dl = r >> 5, sl = r & 31;
        g_eaT[(size_t)k * EE + (size_t)(bd + dl) * NN + bs + sl] = t_sh[k][dl][sl];
    }
}

// Encoder: h = relu(x@W1+b1)@W2+b2, then layer-0 tables (buffer 0). grid=512, block=64
__global__ void __launch_bounds__(H) enc_kernel(
    const float* __restrict__ x,
    const float* __restrict__ ew1, const float* __restrict__ eb1,
    const float* __restrict__ ew2, const float* __restrict__ eb2,
    const float* __restrict__ attW1, const float* __restrict__ attB1,
    const float* __restrict__ valW1, const float* __restrict__ valB1)
{
    int d = blockIdx.x, t = threadIdx.x;
    __shared__ float xs[ED], hid[H], hsn[H];
    if (t < ED) xs[t] = x[d * ED + t];
    __syncthreads();
    float a = eb1[t];
#pragma unroll
    for (int k = 0; k < ED; k++) a += xs[k] * ew1[k * H + t];
    hid[t] = fmaxf(a, 0.f);
    __syncthreads();
    float hv = eb2[t];
#pragma unroll 8
    for (int k = 0; k < H; k++) hv += hid[k] * ew2[k * H + t];
    g_h[d * H + t] = hv;
    hsn[t] = hv;
    __syncthreads();
    compute_tables(d, t, 0, hsn, attW1, attB1, valW1, valB1);
}

// Fused layer: one block per dst node d. 128 threads = 4 warps, all 512 blocks
// co-resident (4/SM) -> single wave. Warp w owns srcs [w*128, w*128+128);
// lane owns 4 srcs. ALL f32x2 operands (weights, ea, softmax weights) are
// stored PRE-DUPLICATED in smem so no MOV-duplication appears in the loops:
// make_float2 from float4 components is register aliasing only.
__global__ void __launch_bounds__(128, 4) layer_kernel(
    const float* __restrict__ attW1e,   // [6,64] edge rows of att_w1[l]
    const float* __restrict__ attW2,    // [64]
    const float* __restrict__ valW1e,   // [6,64] edge rows of val_w1[l]
    const float* __restrict__ valW2, const float* __restrict__ valB2,
    const float* __restrict__ updW1, const float* __restrict__ updB1,
    const float* __restrict__ updW2, const float* __restrict__ updB2,
    const float* __restrict__ lng, const float* __restrict__ lnb,
    const float* __restrict__ nattW1, const float* __restrict__ nattB1,
    const float* __restrict__ nvalW1, const float* __restrict__ nvalB1,
    const float* __restrict__ decW1, const float* __restrict__ decB1,
    const float* __restrict__ decW2, const float* __restrict__ decB2,
    float* __restrict__ out, int rb, int last)
{
    const int d = blockIdx.x;
    const int t = threadIdx.x, w = t >> 5, lane = t & 31;
    const int wb = rb ^ 1;

    __shared__ __align__(16) float4 wa4[H * 4];    // per j: dup pairs (w0,w0,w1,w1)(w2..w3)(w4..w5)(wo,wo,hd,hd)
    __shared__ __align__(16) float4 ea2[NN * 3];   // per s: dup pairs (e0,e0,e1,e1)(e2,e2,e3,e3)(e4,e4,e5,e5)
    __shared__ __align__(16) float2 wexp2[NN];     // per s: duplicated softmax weight (e,e)
    __shared__ float  pm[4], ps[4], pacc[4 * H];
    __shared__ float  part2[2 * H], agg_sh[H], h_sh[H], tmp_sh[H], hid_sh[H], hn_sh[H], red_sh[4];

    // Prologue: duplicated weight table + Hd row
    if (t < H) {
        int j = t;
        float w0 = attW1e[0 * H + j], w1 = attW1e[1 * H + j];
        float w2 = attW1e[2 * H + j], w3 = attW1e[3 * H + j];
        float w4 = attW1e[4 * H + j], w5 = attW1e[5 * H + j];
        float wo = attW2[j];
        float hd = g_Hd[d * H + j];
        wa4[j * 4 + 0] = make_float4(w0, w0, w1, w1);
        wa4[j * 4 + 1] = make_float4(w2, w2, w3, w3);
        wa4[j * 4 + 2] = make_float4(w4, w4, w5, w5);
        wa4[j * 4 + 3] = make_float4(wo, wo, hd, hd);
    }

    const float* HsT = g_HsT[rb];
    const float* AvL = g_Av[rb];
    const int sa = w * 128 + 4 * lane;   // 4 srcs: sa..sa+3

    // Load ea for the 4 srcs (float4 from eaT, contiguous) — registers
    float4 eaq[ED];
#pragma unroll
    for (int k = 0; k < ED; k++)
        eaq[k] = *(const float4*)(g_eaT + (size_t)k * EE + d * NN + sa);

    // Publish DUPLICATED ea pairs for pass 2 (literal component extraction, no selects)
    ea2[(sa + 0) * 3 + 0] = make_float4(eaq[0].x, eaq[0].x, eaq[1].x, eaq[1].x);
    ea2[(sa + 0) * 3 + 1] = make_float4(eaq[2].x, eaq[2].x, eaq[3].x, eaq[3].x);
    ea2[(sa + 0) * 3 + 2] = make_float4(eaq[4].x, eaq[4].x, eaq[5].x, eaq[5].x);
    ea2[(sa + 1) * 3 + 0] = make_float4(eaq[0].y, eaq[0].y, eaq[1].y, eaq[1].y);
    ea2[(sa + 1) * 3 + 1] = make_float4(eaq[2].y, eaq[2].y, eaq[3].y, eaq[3].y);
    ea2[(sa + 1) * 3 + 2] = make_float4(eaq[4].y, eaq[4].y, eaq[5].y, eaq[5].y);
    ea2[(sa + 2) * 3 + 0] = make_float4(eaq[0].z, eaq[0].z, eaq[1].z, eaq[1].z);
    ea2[(sa + 2) * 3 + 1] = make_float4(eaq[2].z, eaq[2].z, eaq[3].z, eaq[3].z);
    ea2[(sa + 2) * 3 + 2] = make_float4(eaq[4].z, eaq[4].z, eaq[5].z, eaq[5].z);
    ea2[(sa + 3) * 3 + 0] = make_float4(eaq[0].w, eaq[0].w, eaq[1].w, eaq[1].w);
    ea2[(sa + 3) * 3 + 1] = make_float4(eaq[2].w, eaq[2].w, eaq[3].w, eaq[3].w);
    ea2[(sa + 3) * 3 + 2] = make_float4(eaq[4].w, eaq[4].w, eaq[5].w, eaq[5].w);

    // Src pairs for f32x2 pass 1: A = (sa, sa+1), B = (sa+2, sa+3) — register aliases
    float2 eA[ED], eB[ED];
#pragma unroll
    for (int k = 0; k < ED; k++) {
        eA[k] = make_float2(eaq[k].x, eaq[k].y);
        eB[k] = make_float2(eaq[k].z, eaq[k].w);
    }
    __syncthreads();

    // ---- Pass 1: attention logits, full j-loop; dup weights via LDS.128 ----
    float2 lgA = make_float2(0.f, 0.f), lgB = make_float2(0.f, 0.f);
    const float2 c02 = make_float2(0.2f, 0.2f);
#pragma unroll 8
    for (int j = 0; j < H; j++) {
        float4 c0 = wa4[j * 4 + 0];
        float4 c1 = wa4[j * 4 + 1];
        float4 c2 = wa4[j * 4 + 2];
        float4 c3 = wa4[j * 4 + 3];
        float4 hs4 = *(const float4*)(HsT + j * NN + sa);
        float2 HD = make_float2(c3.z, c3.w);
        float2 Wo = make_float2(c3.x, c3.y);
        // two 3-deep chains per src pair (4 independent chains)
        float2 zA  = fadd2(make_float2(hs4.x, hs4.y), HD);
        float2 zB  = fadd2(make_float2(hs4.z, hs4.w), HD);
        float2 zA2 = fmul2(eA[3], make_float2(c1.z, c1.w));
        float2 zB2 = fmul2(eB[3], make_float2(c1.z, c1.w));
        zA  = ffma2(eA[0], make_float2(c0.x, c0.y), zA);
        zB  = ffma2(eB[0], make_float2(c0.x, c0.y), zB);
        zA2 = ffma2(eA[4], make_float2(c2.x, c2.y), zA2);
        zB2 = ffma2(eB[4], make_float2(c2.x, c2.y), zB2);
        zA  = ffma2(eA[1], make_float2(c0.z, c0.w), zA);
        zB  = ffma2(eB[1], make_float2(c0.z, c0.w), zB);
        zA2 = ffma2(eA[5], make_float2(c2.z, c2.w), zA2);
        zB2 = ffma2(eB[5], make_float2(c2.z, c2.w), zB2);
        zA  = ffma2(eA[2], make_float2(c1.x, c1.y), zA);
        zB  = ffma2(eB[2], make_float2(c1.x, c1.y), zB);
        zA  = fadd2(zA, zA2);
        zB  = fadd2(zB, zB2);
        // leaky_relu(., 0.2)
        float2 sA = fmul2(zA, c02);
        float2 sB = fmul2(zB, c02);
        zA.x = fmaxf(zA.x, sA.x); zA.y = fmaxf(zA.y, sA.y);
        zB.x = fmaxf(zB.x, sB.x); zB.y = fmaxf(zB.y, sB.y);
        lgA = ffma2(zA, Wo, lgA);
        lgB = ffma2(zB, Wo, lgB);
    }

    // ---- Per-warp register softmax over this warp's 128 srcs ----
    {
        float m = warp_max(fmaxf(fmaxf(lgA.x, lgA.y), fmaxf(lgB.x, lgB.y)));
        float e0 = __expf(lgA.x - m), e1 = __expf(lgA.y - m);
        float e2 = __expf(lgB.x - m), e3 = __expf(lgB.y - m);
        float s_w = warp_sum(e0 + e1 + e2 + e3);
        if (lane == 0) { pm[w] = m; ps[w] = s_w; }
        // duplicated softmax weights: (e,e) per src, two STS.128
        *(float4*)(wexp2 + sa)     = make_float4(e0, e0, e1, e1);
        *(float4*)(wexp2 + sa + 2) = make_float4(e2, e2, e3, e3);
    }
    __syncthreads();

    // ---- Pass 2: alpha-weighted value aggregation (f32x2, 2 dims/lane) ----
    const int j0 = 2 * lane;
    float2 wv[ED];
#pragma unroll
    for (int k = 0; k < ED; k++) wv[k] = *(const float2*)(valW1e + k * H + j0);

    float2 acc0 = make_float2(0.f, 0.f), acc1 = make_float2(0.f, 0.f);
    const int s0 = w * 128;
#pragma unroll 4
    for (int i = 0; i < 128; i += 2) {
#pragma unroll
        for (int u = 0; u < 2; u++) {
            int s = s0 + i + u;
            float4 q0 = ea2[s * 3 + 0];
            float4 q1 = ea2[s * 3 + 1];
            float4 q2 = ea2[s * 3 + 2];
            float2 p = *(const float2*)(AvL + s * H + j0);
            p = ffma2(make_float2(q0.x, q0.y), wv[0], p);
            p = ffma2(make_float2(q0.z, q0.w), wv[1], p);
            p = ffma2(make_float2(q1.x, q1.y), wv[2], p);
            p = ffma2(make_float2(q1.z, q1.w), wv[3], p);
            p = ffma2(make_float2(q2.x, q2.y), wv[4], p);
            p = ffma2(make_float2(q2.z, q2.w), wv[5], p);
            p.x = fmaxf(p.x, 0.f);
            p.y = fmaxf(p.y, 0.f);
            float2 wt2 = wexp2[s];
            if (u) acc1 = ffma2(wt2, p, acc1);
            else   acc0 = ffma2(wt2, p, acc0);
        }
    }
    acc0 = fadd2(acc0, acc1);
    *(float2*)(pacc + w * H + j0) = acc0;
    __syncthreads();

    // ---- Combine 4 warp softmax partials ----
    if (t < H) {
        float M = fmaxf(fmaxf(pm[0], pm[1]), fmaxf(pm[2], pm[3]));
        float sc0 = __expf(pm[0] - M), sc1 = __expf(pm[1] - M);
        float sc2 = __expf(pm[2] - M), sc3 = __expf(pm[3] - M);
        float stot = ps[0] * sc0 + ps[1] * sc1 + ps[2] * sc2 + ps[3] * sc3;
        float a = pacc[0 * H + t] * sc0 + pacc[1 * H + t] * sc1
                + pacc[2 * H + t] * sc2 + pacc[3 * H + t] * sc3;
        agg_sh[t] = a / stot;
        h_sh[t]   = g_h[d * H + t];
    }
    __syncthreads();

    // ---- Node phase, 2-way k-split matvecs over 128 threads ----
    const int o = t & 63, q = t >> 6;

    // stage 1: tmp = val_b2 + agg @ val_w2
    {
        float p = 0.f;
        int k0 = q * 32;
#pragma unroll
        for (int kk = 0; kk < 32; kk++) p += agg_sh[k0 + kk] * valW2[(k0 + kk) * H + o];
        part2[q * H + o] = p;
    }
    __syncthreads();
    if (t < H) tmp_sh[t] = valB2[t] + part2[t] + part2[H + t];
    __syncthreads();

    // stage 2: hid = relu(upd_b1 + [h,tmp] @ upd_w1)
    {
        const float* srcv = (q == 0) ? h_sh : tmp_sh;
        int rbase = q * H;
        float p = 0.f;
#pragma unroll
        for (int kk = 0; kk < 64; kk++) p += srcv[kk] * updW1[(rbase + kk) * H + o];
        part2[q * H + o] = p;
    }
    __syncthreads();
    if (t < H) hid_sh[t] = fmaxf(updB1[t] + part2[t] + part2[H + t], 0.f);
    __syncthreads();

    // stage 3: u = upd_b2 + hid @ upd_w2
    {
        float p = 0.f;
        int k0 = q * 32;
#pragma unroll
        for (int kk = 0; kk < 32; kk++) p += hid_sh[k0 + kk] * updW2[(k0 + kk) * H + o];
        part2[q * H + o] = p;
    }
    __syncthreads();

    // residual + LayerNorm (threads 0..63 = warps 0,1; fused sum/sumsq)
    float r = 0.f, dr = 0.f;
    if (t < H) {
        float u = updB2[t] + part2[t] + part2[H + t];
        r = u + h_sh[t];
        float s1 = warp_sum(r);
        float s2 = warp_sum(r * r);
        if (lane == 0) { red_sh[w] = s1; red_sh[w + 2] = s2; }
    }
    __syncthreads();
    if (t < H) {
        float mu  = (red_sh[0] + red_sh[1]) * (1.0f / H);
        float ex2 = (red_sh[2] + red_sh[3]) * (1.0f / H);
        float var = ex2 - mu * mu;
        dr = r - mu;
        float hn = lng[t] * dr * rsqrtf(var + LN_EPS) + lnb[t];
        hn_sh[t] = hn;
        if (!last) g_h[d * H + t] = hn;
    }
    __syncthreads();

    if (!last) {
        if (t < H)
            compute_tables(d, t, wb, hn_sh, nattW1, nattB1, nvalW1, nvalB1);
    } else {
        if (t < H) {
            float dh = decB1[t];
#pragma unroll 8
            for (int k = 0; k < H; k++) dh += hn_sh[k] * decW1[k * H + t];
            dh = fmaxf(dh, 0.f);
            float p = dh * decW2[t];
            float psum = warp_sum(p);
            if (lane == 0) red_sh[w] = psum;
        }
        __syncthreads();
        if (t == 0) out[d] = red_sh[0] + red_sh[1] + decB2[0];
    }
}

extern "C" void kernel_launch(void* const* d_in, const int* in_sizes, int n_in,
                              void* d_out, int out_size)
{
    const float* x      = (const float*)d_in[0];
    const float* ea     = (const float*)d_in[1];
    const float* enc_w1 = (const float*)d_in[2];
    const float* enc_b1 = (const float*)d_in[3];
    const float* enc_w2 = (const float*)d_in[4];
    const float* enc_b2 = (const float*)d_in[5];
    const float* att_w1 = (const float*)d_in[6];   // [4,134,64]
    const float* att_b1 = (const float*)d_in[7];   // [4,64]
    const float* att_w2 = (const float*)d_in[8];   // [4,64,1]
    // d_in[9] = att_b2 — cancels inside softmax, unused
    const float* val_w1 = (const float*)d_in[10];  // [4,70,64]
    const float* val_b1 = (const float*)d_in[11];  // [4,64]
    const float* val_w2 = (const float*)d_in[12];  // [4,64,64]
    const float* val_b2 = (const float*)d_in[13];  // [4,64]
    const float* upd_w1 = (const float*)d_in[14];  // [4,128,64]
    const float* upd_b1 = (const float*)d_in[15];  // [4,64]
    const float* upd_w2 = (const float*)d_in[16];  // [4,64,64]
    const float* upd_b2 = (const float*)d_in[17];  // [4,64]
    const float* ln_g   = (const float*)d_in[18];  // [4,64]
    const float* ln_b   = (const float*)d_in[19];  // [4,64]
    const float* dec_w1 = (const float*)d_in[20];
    const float* dec_b1 = (const float*)d_in[21];
    const float* dec_w2 = (const float*)d_in[22];
    const float* dec_b2 = (const float*)d_in[23];
    // d_in[24] = edge_index: src=e/512, dst=e%512 (structure exploited directly)

    float* out = (float*)d_out;

    ea_transpose_kernel<<<dim3(16, 16), 256>>>(ea);
    enc_kernel<<<NN, H>>>(x, enc_w1, enc_b1, enc_w2, enc_b2,
                          att_w1, att_b1, val_w1, val_b1);

    for (int l = 0; l < NL; l++) {
        int last = (l == NL - 1);
        int nl = (l + 1) % NL;      // dummy-but-valid pointers on last layer
        int rb = l & 1;             // enc wrote buffer 0; layer l reads l&1, writes (l&1)^1
        layer_kernel<<<NN, 128>>>(att_w1 + (l * 134 + 128) * H,
                                  att_w2 + l * H,
                                  val_w1 + (l * 70 + 64) * H,
                                  val_w2 + l * H * H, val_b2 + l * H,
                                  upd_w1 + l * 2 * H * H, upd_b1 + l * H,
                                  upd_w2 + l * H * H, upd_b2 + l * H,
                                  ln_g + l * H, ln_b + l * H,
                                  att_w1 + nl * 134 * H, att_b1 + nl * H,
                                  val_w1 + nl * 70 * H, val_b1 + nl * H,
                                  dec_w1, dec_b1, dec_w2, dec_b2,
                                  out, rb, last);
    }
}